// round 2
// baseline (speedup 1.0000x reference)
#include <cuda_runtime.h>
#include <math.h>

#define B_  32
#define C_  256
#define H_  128
#define W_  128
#define HW  (H_ * W_)
#define HW4 (HW / 4)

// Partial reductions (2-way channel split) + gate. All L2-resident (2 MB each).
__device__ float g_psum0[B_ * HW];
__device__ float g_psum1[B_ * HW];
__device__ float g_pmax0[B_ * HW];
__device__ float g_pmax1[B_ * HW];
__device__ float g_gate [B_ * HW];

// ---------------------------------------------------------------------------
// K1: channel-wise partial mean & max over y. 2-way channel split for occupancy.
// thread -> (half, b, pixel-quad); each reduces 128 channels.
// ---------------------------------------------------------------------------
__global__ void __launch_bounds__(256) reduce_kernel(const float* __restrict__ y) {
    int idx = blockIdx.x * blockDim.x + threadIdx.x;     // over 2 * B * HW4
    if (idx >= 2 * B_ * HW4) return;
    int half = idx / (B_ * HW4);
    int rem  = idx - half * (B_ * HW4);
    int b    = rem / HW4;
    int p4   = rem - b * HW4;

    const float4* base = reinterpret_cast<const float4*>(y)
                       + (size_t)b * C_ * HW4 + (size_t)half * 128 * HW4 + p4;

    float4 s = make_float4(0.f, 0.f, 0.f, 0.f);
    float4 m = make_float4(-INFINITY, -INFINITY, -INFINITY, -INFINITY);

    #pragma unroll 8
    for (int c = 0; c < 128; c++) {
        float4 v = __ldcs(base + (size_t)c * HW4);
        s.x += v.x; s.y += v.y; s.z += v.z; s.w += v.w;
        m.x = fmaxf(m.x, v.x); m.y = fmaxf(m.y, v.y);
        m.z = fmaxf(m.z, v.z); m.w = fmaxf(m.w, v.w);
    }

    float4* psum = half ? reinterpret_cast<float4*>(g_psum1)
                        : reinterpret_cast<float4*>(g_psum0);
    float4* pmax = half ? reinterpret_cast<float4*>(g_pmax1)
                        : reinterpret_cast<float4*>(g_pmax0);
    int pi = b * HW4 + p4;
    psum[pi] = s;
    pmax[pi] = m;
}

// ---------------------------------------------------------------------------
// K2: combine partials + 3x3 conv + sigmoid -> gate. One thread/pixel. L2-bound,
// tiny.
// ---------------------------------------------------------------------------
__global__ void __launch_bounds__(256) gate_kernel(const float* __restrict__ conv_w) {
    int idx = blockIdx.x * blockDim.x + threadIdx.x;     // over B*HW
    if (idx >= B_ * HW) return;
    int b  = idx / HW;
    int hw = idx - b * HW;
    int h  = hw / W_;
    int w  = hw - h * W_;

    const float inv = 1.0f / (float)C_;
    float acc = 0.f;
    #pragma unroll
    for (int kh = -1; kh <= 1; kh++) {
        int hh = h + kh;
        if (hh < 0 || hh >= H_) continue;
        #pragma unroll
        for (int kw = -1; kw <= 1; kw++) {
            int ww = w + kw;
            if (ww < 0 || ww >= W_) continue;
            int si = b * HW + hh * W_ + ww;
            int ki = (kh + 1) * 3 + (kw + 1);
            float avg = (g_psum0[si] + g_psum1[si]) * inv;
            float mx  = fmaxf(g_pmax0[si], g_pmax1[si]);
            acc = fmaf(avg, conv_w[ki],     acc);
            acc = fmaf(mx,  conv_w[9 + ki], acc);
        }
    }
    g_gate[idx] = 1.0f / (1.0f + expf(-acc));
}

// ---------------------------------------------------------------------------
// K3: out = x * gate.  Thread owns a pixel-quad, loads its gate ONCE into
// registers, then streams 64 channels (C split 4-way across threads).
// ---------------------------------------------------------------------------
__global__ void __launch_bounds__(256) mul_kernel(const float* __restrict__ x,
                                                  float* __restrict__ out) {
    int idx = blockIdx.x * blockDim.x + threadIdx.x;     // over B * 4 * HW4
    if (idx >= B_ * 4 * HW4) return;
    int p4 = idx % HW4;
    int t  = idx / HW4;
    int q  = t % 4;            // channel chunk (64 channels each)
    int b  = t / 4;

    float4 g = reinterpret_cast<const float4*>(g_gate)[b * HW4 + p4];

    size_t off = ((size_t)b * C_ + (size_t)q * 64) * HW4 + p4;
    const float4* xin = reinterpret_cast<const float4*>(x)   + off;
    float4*       dst = reinterpret_cast<float4*>(out)       + off;

    #pragma unroll 8
    for (int c = 0; c < 64; c++) {
        float4 xv = __ldcs(xin + (size_t)c * HW4);
        float4 o;
        o.x = xv.x * g.x; o.y = xv.y * g.y;
        o.z = xv.z * g.z; o.w = xv.w * g.w;
        __stcs(dst + (size_t)c * HW4, o);
    }
}

// ---------------------------------------------------------------------------
extern "C" void kernel_launch(void* const* d_in, const int* in_sizes, int n_in,
                              void* d_out, int out_size) {
    const float* x      = (const float*)d_in[0];
    const float* y      = (const float*)d_in[1];
    const float* conv_w = (const float*)d_in[2];
    float* out          = (float*)d_out;

    {
        int n = 2 * B_ * HW4;           // 262144 threads
        reduce_kernel<<<(n + 255) / 256, 256>>>(y);
    }
    {
        int n = B_ * HW;                // 524288 threads
        gate_kernel<<<(n + 255) / 256, 256>>>(conv_w);
    }
    {
        int n = B_ * 4 * HW4;           // 524288 threads
        mul_kernel<<<(n + 255) / 256, 256>>>(x, out);
    }
}

// round 3
// speedup vs baseline: 1.0298x; 1.0298x over previous
#include <cuda_runtime.h>
#include <math.h>

#define B_  32
#define C_  256
#define H_  128
#define W_  128
#define HW  (H_ * W_)
#define HW4 (HW / 4)

// Partial reductions (2-way channel split) + gate. All L2-resident.
__device__ float g_psum0[B_ * HW];
__device__ float g_psum1[B_ * HW];
__device__ float g_pmax0[B_ * HW];
__device__ float g_pmax1[B_ * HW];
__device__ float g_gate [B_ * HW];

// ---------------------------------------------------------------------------
// K1: channel-wise partial mean & max over y. 2-way channel split for occupancy.
// ---------------------------------------------------------------------------
__global__ void __launch_bounds__(256) reduce_kernel(const float* __restrict__ y) {
    int idx = blockIdx.x * blockDim.x + threadIdx.x;     // over 2 * B * HW4
    if (idx >= 2 * B_ * HW4) return;
    int half = idx / (B_ * HW4);
    int rem  = idx - half * (B_ * HW4);
    int b    = rem / HW4;
    int p4   = rem - b * HW4;

    const float4* base = reinterpret_cast<const float4*>(y)
                       + (size_t)b * C_ * HW4 + (size_t)half * 128 * HW4 + p4;

    float4 s = make_float4(0.f, 0.f, 0.f, 0.f);
    float4 m = make_float4(-INFINITY, -INFINITY, -INFINITY, -INFINITY);

    #pragma unroll 8
    for (int c = 0; c < 128; c++) {
        float4 v = __ldcs(base + (size_t)c * HW4);
        s.x += v.x; s.y += v.y; s.z += v.z; s.w += v.w;
        m.x = fmaxf(m.x, v.x); m.y = fmaxf(m.y, v.y);
        m.z = fmaxf(m.z, v.z); m.w = fmaxf(m.w, v.w);
    }

    float4* psum = half ? reinterpret_cast<float4*>(g_psum1)
                        : reinterpret_cast<float4*>(g_psum0);
    float4* pmax = half ? reinterpret_cast<float4*>(g_pmax1)
                        : reinterpret_cast<float4*>(g_pmax0);
    int pi = b * HW4 + p4;
    psum[pi] = s;
    pmax[pi] = m;
}

// ---------------------------------------------------------------------------
// K2: smem-tiled combine + 3x3 conv + sigmoid -> gate.
// 32x32 output tile per block, 34x34 halo in smem. Grid = B * 4 * 4.
// ---------------------------------------------------------------------------
__global__ void __launch_bounds__(256) gate_kernel(const float* __restrict__ conv_w) {
    __shared__ float s_avg[34][36];   // +pad to dodge bank conflicts
    __shared__ float s_max[34][36];

    int blk = blockIdx.x;             // b*16 + th*4 + tw
    int b  = blk >> 4;
    int r  = blk & 15;
    int th = r >> 2;
    int tw = r & 3;
    int h0 = th * 32 - 1;
    int w0 = tw * 32 - 1;

    const float inv = 1.0f / (float)C_;

    // Cooperative halo load: combine partials on the fly; zero outside (conv
    // zero-padding).
    for (int i = threadIdx.x; i < 34 * 34; i += 256) {
        int lh = i / 34;
        int lw = i - lh * 34;
        int h  = h0 + lh;
        int w  = w0 + lw;
        float a = 0.f, m = 0.f;
        if (h >= 0 && h < H_ && w >= 0 && w < W_) {
            int si = b * HW + h * W_ + w;
            a = (g_psum0[si] + g_psum1[si]) * inv;
            m = fmaxf(g_pmax0[si], g_pmax1[si]);
        }
        s_avg[lh][lw] = a;
        s_max[lh][lw] = m;
    }
    __syncthreads();

    float wa[9], wm[9];
    #pragma unroll
    for (int k = 0; k < 9; k++) { wa[k] = conv_w[k]; wm[k] = conv_w[9 + k]; }

    for (int i = threadIdx.x; i < 32 * 32; i += 256) {
        int lh = i >> 5;
        int lw = i & 31;
        float acc = 0.f;
        #pragma unroll
        for (int kh = 0; kh < 3; kh++)
            #pragma unroll
            for (int kw = 0; kw < 3; kw++) {
                acc = fmaf(s_avg[lh + kh][lw + kw], wa[kh * 3 + kw], acc);
                acc = fmaf(s_max[lh + kh][lw + kw], wm[kh * 3 + kw], acc);
            }
        int h = th * 32 + lh;
        int w = tw * 32 + lw;
        g_gate[b * HW + h * W_ + w] = 1.0f / (1.0f + expf(-acc));
    }
}

// ---------------------------------------------------------------------------
// K3: out = x * gate.  Pure linear float4 stream (R1 form — fastest measured).
// Gate float4 comes from L2 (2 MB resident).
// ---------------------------------------------------------------------------
__global__ void __launch_bounds__(256) mul_kernel(const float* __restrict__ x,
                                                  float* __restrict__ out) {
    long long idx = (long long)blockIdx.x * blockDim.x + threadIdx.x;  // B*C*HW4
    const long long total4 = (long long)B_ * C_ * HW4;
    if (idx >= total4) return;

    int p4 = (int)(idx % HW4);
    int b  = (int)(idx / ((long long)C_ * HW4));

    float4 g  = reinterpret_cast<const float4*>(g_gate)[b * HW4 + p4];  // L2 hit
    float4 xv = __ldcs(reinterpret_cast<const float4*>(x) + idx);
    float4 o;
    o.x = xv.x * g.x; o.y = xv.y * g.y; o.z = xv.z * g.z; o.w = xv.w * g.w;
    __stcs(reinterpret_cast<float4*>(out) + idx, o);
}

// ---------------------------------------------------------------------------
extern "C" void kernel_launch(void* const* d_in, const int* in_sizes, int n_in,
                              void* d_out, int out_size) {
    const float* x      = (const float*)d_in[0];
    const float* y      = (const float*)d_in[1];
    const float* conv_w = (const float*)d_in[2];
    float* out          = (float*)d_out;

    {
        int n = 2 * B_ * HW4;           // 262144 threads
        reduce_kernel<<<(n + 255) / 256, 256>>>(y);
    }
    {
        gate_kernel<<<B_ * 16, 256>>>(conv_w);   // 512 blocks, 32x32 tiles
    }
    {
        long long n = (long long)B_ * C_ * HW4;  // 33554432 threads
        mul_kernel<<<(int)((n + 255) / 256), 256>>>(x, out);
    }
}

// round 4
// speedup vs baseline: 1.0489x; 1.0185x over previous
#include <cuda_runtime.h>
#include <math.h>

#define B_  32
#define C_  256
#define H_  128
#define W_  128
#define HW  (H_ * W_)
#define HW4 (HW / 4)
#define NSPLIT 8            // channel split factor (32 channels per thread)

// Partial reductions (8-way channel split) + gate. 8*2*2MB = 32MB scratch.
__device__ float g_psum[NSPLIT][B_ * HW];
__device__ float g_pmax[NSPLIT][B_ * HW];
__device__ float g_gate [B_ * HW];

// ---------------------------------------------------------------------------
// K1: channel-wise partial mean & max over y. 8-way split -> 4096 blocks
// (~4 waves) to smooth the single-wave tail-spread that idles DRAM.
// ---------------------------------------------------------------------------
__global__ void __launch_bounds__(256) reduce_kernel(const float* __restrict__ y) {
    int idx = blockIdx.x * blockDim.x + threadIdx.x;     // over NSPLIT * B * HW4
    int part = idx / (B_ * HW4);
    int rem  = idx - part * (B_ * HW4);
    int b    = rem / HW4;
    int p4   = rem - b * HW4;

    const float4* base = reinterpret_cast<const float4*>(y)
                       + (size_t)b * C_ * HW4 + (size_t)part * (C_ / NSPLIT) * HW4 + p4;

    float4 s = make_float4(0.f, 0.f, 0.f, 0.f);
    float4 m = make_float4(-INFINITY, -INFINITY, -INFINITY, -INFINITY);

    #pragma unroll 8
    for (int c = 0; c < C_ / NSPLIT; c++) {
        float4 v = __ldcs(base + (size_t)c * HW4);
        s.x += v.x; s.y += v.y; s.z += v.z; s.w += v.w;
        m.x = fmaxf(m.x, v.x); m.y = fmaxf(m.y, v.y);
        m.z = fmaxf(m.z, v.z); m.w = fmaxf(m.w, v.w);
    }

    int pi = b * HW4 + p4;
    reinterpret_cast<float4*>(g_psum[part])[pi] = s;
    reinterpret_cast<float4*>(g_pmax[part])[pi] = m;
}

// ---------------------------------------------------------------------------
// K2: combine 8 partials + 3x3 conv + sigmoid -> gate. smem-tiled 32x32.
// ---------------------------------------------------------------------------
__global__ void __launch_bounds__(256) gate_kernel(const float* __restrict__ conv_w) {
    __shared__ float s_avg[34][36];
    __shared__ float s_max[34][36];

    int blk = blockIdx.x;             // b*16 + th*4 + tw
    int b  = blk >> 4;
    int r  = blk & 15;
    int th = r >> 2;
    int tw = r & 3;
    int h0 = th * 32 - 1;
    int w0 = tw * 32 - 1;

    const float inv = 1.0f / (float)C_;

    for (int i = threadIdx.x; i < 34 * 34; i += 256) {
        int lh = i / 34;
        int lw = i - lh * 34;
        int h  = h0 + lh;
        int w  = w0 + lw;
        float a = 0.f, m = 0.f;
        if (h >= 0 && h < H_ && w >= 0 && w < W_) {
            int si = b * HW + h * W_ + w;
            float ssum = 0.f, smax = -INFINITY;
            #pragma unroll
            for (int p = 0; p < NSPLIT; p++) {
                ssum += g_psum[p][si];
                smax  = fmaxf(smax, g_pmax[p][si]);
            }
            a = ssum * inv;
            m = smax;
        }
        s_avg[lh][lw] = a;
        s_max[lh][lw] = m;
    }
    __syncthreads();

    float wa[9], wm[9];
    #pragma unroll
    for (int k = 0; k < 9; k++) { wa[k] = conv_w[k]; wm[k] = conv_w[9 + k]; }

    for (int i = threadIdx.x; i < 32 * 32; i += 256) {
        int lh = i >> 5;
        int lw = i & 31;
        float acc = 0.f;
        #pragma unroll
        for (int kh = 0; kh < 3; kh++)
            #pragma unroll
            for (int kw = 0; kw < 3; kw++) {
                acc = fmaf(s_avg[lh + kh][lw + kw], wa[kh * 3 + kw], acc);
                acc = fmaf(s_max[lh + kh][lw + kw], wm[kh * 3 + kw], acc);
            }
        int h = th * 32 + lh;
        int w = tw * 32 + lw;
        g_gate[b * HW + h * W_ + w] = 1.0f / (1.0f + expf(-acc));
    }
}

// ---------------------------------------------------------------------------
// K3: out = x * gate.  2D grid: blockIdx.y = b*C + c plane, blockIdx.x tiles
// HW4. Each thread handles 2 float4s, 256 apart (both per-instruction
// coalesced), doubling per-thread MLP. No int64 div/mod.
// ---------------------------------------------------------------------------
__global__ void __launch_bounds__(256) mul_kernel(const float* __restrict__ x,
                                                  float* __restrict__ out) {
    int plane = blockIdx.y;                    // b*C + c  (0..8191)
    int b     = plane >> 8;                    // / C_
    int p4    = blockIdx.x * 512 + threadIdx.x;   // first of two float4s

    size_t base = (size_t)plane * HW4;
    const float4* xin = reinterpret_cast<const float4*>(x)   + base;
    float4*       dst = reinterpret_cast<float4*>(out)       + base;
    const float4* gp  = reinterpret_cast<const float4*>(g_gate) + (size_t)b * HW4;

    float4 g0  = gp[p4];
    float4 g1  = gp[p4 + 256];
    float4 x0  = __ldcs(xin + p4);
    float4 x1  = __ldcs(xin + p4 + 256);

    float4 o0, o1;
    o0.x = x0.x * g0.x; o0.y = x0.y * g0.y; o0.z = x0.z * g0.z; o0.w = x0.w * g0.w;
    o1.x = x1.x * g1.x; o1.y = x1.y * g1.y; o1.z = x1.z * g1.z; o1.w = x1.w * g1.w;

    __stcs(dst + p4,       o0);
    __stcs(dst + p4 + 256, o1);
}

// ---------------------------------------------------------------------------
extern "C" void kernel_launch(void* const* d_in, const int* in_sizes, int n_in,
                              void* d_out, int out_size) {
    const float* x      = (const float*)d_in[0];
    const float* y      = (const float*)d_in[1];
    const float* conv_w = (const float*)d_in[2];
    float* out          = (float*)d_out;

    {
        int n = NSPLIT * B_ * HW4;      // 1048576 threads, 4096 blocks
        reduce_kernel<<<n / 256, 256>>>(y);
    }
    {
        gate_kernel<<<B_ * 16, 256>>>(conv_w);   // 512 blocks
    }
    {
        dim3 grid(HW4 / 512, B_ * C_);  // (8, 8192)
        mul_kernel<<<grid, 256>>>(x, out);
    }
}

// round 5
// speedup vs baseline: 1.0750x; 1.0249x over previous
#include <cuda_runtime.h>
#include <math.h>

#define B_  32
#define C_  256
#define H_  128
#define W_  128
#define HW  (H_ * W_)
#define HW4 (HW / 4)
#define NSPLIT 8            // channel parts per pixel-quad (32 channels each)

// Combined reductions + gate. All small & L2-resident.
__device__ float g_avg [B_ * HW];
__device__ float g_max [B_ * HW];
__device__ float g_gate[B_ * HW];

// ---------------------------------------------------------------------------
// K1: channel-wise mean & max over y, combined IN-KERNEL via smem.
// Block = 8 channel-parts x 32 pixel-quads. Writes only final avg/max (8 MB
// total instead of 32 MB of partials).
// ---------------------------------------------------------------------------
__global__ void __launch_bounds__(256) reduce_kernel(const float* __restrict__ y) {
    __shared__ float4 s_s[NSPLIT][32];
    __shared__ float4 s_m[NSPLIT][32];

    int lane = threadIdx.x & 31;
    int part = threadIdx.x >> 5;
    int q    = blockIdx.x * 32 + lane;      // global pixel-quad index (B*HW4)
    int b    = q >> 12;                      // / HW4 (4096)
    int p4   = q & 4095;

    const float4* base = reinterpret_cast<const float4*>(y)
                       + ((size_t)b * C_ + (size_t)part * (C_ / NSPLIT)) * HW4 + p4;

    float4 s = make_float4(0.f, 0.f, 0.f, 0.f);
    float4 m = make_float4(-INFINITY, -INFINITY, -INFINITY, -INFINITY);

    #pragma unroll 8
    for (int c = 0; c < C_ / NSPLIT; c++) {
        float4 v = __ldcs(base + (size_t)c * HW4);
        s.x += v.x; s.y += v.y; s.z += v.z; s.w += v.w;
        m.x = fmaxf(m.x, v.x); m.y = fmaxf(m.y, v.y);
        m.z = fmaxf(m.z, v.z); m.w = fmaxf(m.w, v.w);
    }

    s_s[part][lane] = s;
    s_m[part][lane] = m;
    __syncthreads();

    if (part == 0) {
        #pragma unroll
        for (int p = 1; p < NSPLIT; p++) {
            float4 t  = s_s[p][lane];
            float4 tm = s_m[p][lane];
            s.x += t.x; s.y += t.y; s.z += t.z; s.w += t.w;
            m.x = fmaxf(m.x, tm.x); m.y = fmaxf(m.y, tm.y);
            m.z = fmaxf(m.z, tm.z); m.w = fmaxf(m.w, tm.w);
        }
        const float inv = 1.0f / (float)C_;
        s.x *= inv; s.y *= inv; s.z *= inv; s.w *= inv;
        reinterpret_cast<float4*>(g_avg)[q] = s;
        reinterpret_cast<float4*>(g_max)[q] = m;
    }
}

// ---------------------------------------------------------------------------
// K2: 3x3 conv + sigmoid -> gate. smem-tiled 32x32 with 34x34 halo.
// ---------------------------------------------------------------------------
__global__ void __launch_bounds__(256) gate_kernel(const float* __restrict__ conv_w) {
    __shared__ float s_avg[34][36];
    __shared__ float s_max[34][36];

    int blk = blockIdx.x;             // b*16 + th*4 + tw
    int b  = blk >> 4;
    int r  = blk & 15;
    int th = r >> 2;
    int tw = r & 3;
    int h0 = th * 32 - 1;
    int w0 = tw * 32 - 1;

    for (int i = threadIdx.x; i < 34 * 34; i += 256) {
        int lh = i / 34;
        int lw = i - lh * 34;
        int h  = h0 + lh;
        int w  = w0 + lw;
        float a = 0.f, m = 0.f;
        if (h >= 0 && h < H_ && w >= 0 && w < W_) {
            int si = b * HW + h * W_ + w;
            a = g_avg[si];
            m = g_max[si];
        }
        s_avg[lh][lw] = a;
        s_max[lh][lw] = m;
    }
    __syncthreads();

    float wa[9], wm[9];
    #pragma unroll
    for (int k = 0; k < 9; k++) { wa[k] = conv_w[k]; wm[k] = conv_w[9 + k]; }

    for (int i = threadIdx.x; i < 32 * 32; i += 256) {
        int lh = i >> 5;
        int lw = i & 31;
        float acc = 0.f;
        #pragma unroll
        for (int kh = 0; kh < 3; kh++)
            #pragma unroll
            for (int kw = 0; kw < 3; kw++) {
                acc = fmaf(s_avg[lh + kh][lw + kw], wa[kh * 3 + kw], acc);
                acc = fmaf(s_max[lh + kh][lw + kw], wm[kh * 3 + kw], acc);
            }
        int h = th * 32 + lh;
        int w = tw * 32 + lw;
        g_gate[b * HW + h * W_ + w] = 1.0f / (1.0f + expf(-acc));
    }
}

// ---------------------------------------------------------------------------
// K3: out = x * gate.  2D grid, 2 independent float4 pairs per thread.
// ---------------------------------------------------------------------------
__global__ void __launch_bounds__(256) mul_kernel(const float* __restrict__ x,
                                                  float* __restrict__ out) {
    int plane = blockIdx.y;                    // b*C + c  (0..8191)
    int b     = plane >> 8;                    // / C_
    int p4    = blockIdx.x * 512 + threadIdx.x;

    size_t base = (size_t)plane * HW4;
    const float4* xin = reinterpret_cast<const float4*>(x)   + base;
    float4*       dst = reinterpret_cast<float4*>(out)       + base;
    const float4* gp  = reinterpret_cast<const float4*>(g_gate) + (size_t)b * HW4;

    float4 g0  = gp[p4];
    float4 g1  = gp[p4 + 256];
    float4 x0  = __ldcs(xin + p4);
    float4 x1  = __ldcs(xin + p4 + 256);

    float4 o0, o1;
    o0.x = x0.x * g0.x; o0.y = x0.y * g0.y; o0.z = x0.z * g0.z; o0.w = x0.w * g0.w;
    o1.x = x1.x * g1.x; o1.y = x1.y * g1.y; o1.z = x1.z * g1.z; o1.w = x1.w * g1.w;

    __stcs(dst + p4,       o0);
    __stcs(dst + p4 + 256, o1);
}

// ---------------------------------------------------------------------------
extern "C" void kernel_launch(void* const* d_in, const int* in_sizes, int n_in,
                              void* d_out, int out_size) {
    const float* x      = (const float*)d_in[0];
    const float* y      = (const float*)d_in[1];
    const float* conv_w = (const float*)d_in[2];
    float* out          = (float*)d_out;

    {
        int blocks = B_ * HW4 / 32;     // 4096 blocks x 256 threads
        reduce_kernel<<<blocks, 256>>>(y);
    }
    {
        gate_kernel<<<B_ * 16, 256>>>(conv_w);   // 512 blocks
    }
    {
        dim3 grid(HW4 / 512, B_ * C_);  // (8, 8192)
        mul_kernel<<<grid, 256>>>(x, out);
    }
}